// round 17
// baseline (speedup 1.0000x reference)
#include <cuda_runtime.h>
#include <cuda_fp16.h>
#include <cstdint>
#include <cstddef>

#define NMAX 100000
#define EMAX 3200000
#define CH 128
#define CAP 64           // padded-CSR slots per node
#define OVF_CAP 65536

// ---------------- scratch ----------------
// NOTE: g_cur / g_novf are self-resetting (aggr / gemm2 restore them to 0),
// so no init pass is needed for them; device globals are zero-init at load.
__device__ __half g_t_h[(size_t)NMAX * CH];     // t = x @ W_theta^T (fp16)
__device__ __half g_aggr_h[(size_t)NMAX * CH];  // aggr output (fp16)
__device__ int    g_cur[NMAX];
__device__ int    g_csr[(size_t)NMAX * CAP];
__device__ int    g_novf;
__device__ int    g_ovf_r[OVF_CAP];
__device__ int    g_ovf_c[OVF_CAP];
__device__ __half g_w[2 * CH * CH];             // fp16 W (theta, phi)

// ---------------- init: convert W to fp16 (only gemm1 depends on this) ----------------
__global__ void init_kernel(const float* __restrict__ Wt, const float* __restrict__ Wp) {
    int i = blockIdx.x * blockDim.x + threadIdx.x;
    if (i < 2 * CH * CH) {
        float v = (i < CH * CH) ? Wt[i] : Wp[i - CH * CH];
        g_w[i] = __float2half_rn(v);
    }
}

// ---------------- padded-CSR scatter (4 edges/thread) ----------------
__device__ __forceinline__ void push_edge(int r, int c) {
    int p = atomicAdd(&g_cur[r], 1);
    if (p < CAP) {
        g_csr[(size_t)r * CAP + p] = c;
    } else {
        int o = atomicAdd(&g_novf, 1);
        if (o < OVF_CAP) { g_ovf_r[o] = r; g_ovf_c[o] = c; }
    }
}

__global__ void scatter_kernel(const int* __restrict__ row, const int* __restrict__ col, int E) {
    int t = blockIdx.x * blockDim.x + threadIdx.x;
    int e0 = t * 4;
    if (e0 >= E) return;
    if (((E & 3) == 0) && (e0 + 4 <= E)) {
        int4 r4 = *reinterpret_cast<const int4*>(row + e0);
        int4 c4 = *reinterpret_cast<const int4*>(col + e0);
        push_edge(r4.x, c4.x);
        push_edge(r4.y, c4.y);
        push_edge(r4.z, c4.z);
        push_edge(r4.w, c4.w);
    } else {
        int lim = min(e0 + 4, E);
        for (int e = e0; e < lim; e++) push_edge(row[e], col[e]);
    }
}

// ---------------- HMMA helpers ----------------
__device__ __forceinline__ uint32_t smem_u32(const void* p) {
    uint32_t a;
    asm("{ .reg .u64 t; cvta.to.shared.u64 t, %1; cvt.u32.u64 %0, t; }" : "=r"(a) : "l"(p));
    return a;
}

__device__ __forceinline__ void ldsm_x4(uint32_t addr, uint32_t& r0, uint32_t& r1,
                                        uint32_t& r2, uint32_t& r3) {
    asm volatile("ldmatrix.sync.aligned.m8n8.x4.shared.b16 {%0,%1,%2,%3}, [%4];"
                 : "=r"(r0), "=r"(r1), "=r"(r2), "=r"(r3) : "r"(addr));
}

__device__ __forceinline__ void mma_f16(float* c, const uint32_t* a, const uint32_t* b) {
    asm volatile(
        "mma.sync.aligned.m16n8k16.row.col.f32.f16.f16.f32 "
        "{%0,%1,%2,%3}, {%4,%5,%6,%7}, {%8,%9}, {%0,%1,%2,%3};"
        : "+f"(c[0]), "+f"(c[1]), "+f"(c[2]), "+f"(c[3])
        : "r"(a[0]), "r"(a[1]), "r"(a[2]), "r"(a[3]), "r"(b[0]), "r"(b[1]));
}

// ---------------- persistent tensor-core GEMM: C[M,128] = A[M,128] @ W^T ----------------
// Pure fp16, single MMA pass. W staged ONCE per CTA; tiles processed in a
// grid-strided loop. SMEM: A tile + W tile (2 CTAs/SM).
#define ROWB 272
#define TILEB (128 * ROWB)
#define AS_T  0
#define WS_T  TILEB
#define GSM_TOTAL (2 * TILEB)     // 69632

__global__ __launch_bounds__(256, 2) void tc_gemm_kernel(
    const float* __restrict__ A32, const __half* __restrict__ A16,
    float* __restrict__ C, __half* __restrict__ Ch,
    int M, int which, int ntiles, int reset_ovf)
{
    extern __shared__ char smem[];
    const uint32_t sb = smem_u32(smem);
    const int tid = threadIdx.x;
    const int w = tid >> 5;
    const int lane = tid & 31;

    if (reset_ovf && blockIdx.x == 0 && tid == 0) g_novf = 0;

    // stage W once (fp16 in global)
    const uint4* wsrc = reinterpret_cast<const uint4*>(g_w + (size_t)which * CH * CH);
    #pragma unroll
    for (int it = 0; it < 8; it++) {
        int q = tid + it * 256;
        int r = q >> 4;
        int u = q & 15;
        *reinterpret_cast<uint4*>(smem + WS_T + r * ROWB + u * 16) = wsrc[q];
    }

    // per-lane constants
    const int mw0 = (w & 3) * 32;
    const int nw0 = (w >> 2) * 64;
    const int a_row = mw0 + (lane & 15);
    const int a_kof = (lane >> 4) * 8;
    const int b_nof = (lane & 7) + ((lane >> 4) ? 8 : 0);
    const int b_kof = ((lane >> 3) & 1) * 8;
    const uint32_t a_base = sb + AS_T + a_row * ROWB + a_kof * 2;
    const uint32_t b_base = sb + WS_T + (nw0 + b_nof) * ROWB + b_kof * 2;
    const int mq = lane >> 2;
    const int nq = (lane & 3) * 2;

    for (int tile = blockIdx.x; tile < ntiles; tile += gridDim.x) {
        const int m0 = tile * 128;

        // stage A -> fp16 smem tile
        if (A32) {
            #pragma unroll
            for (int it = 0; it < 16; it++) {
                int q = tid + it * 256;          // 0..4095 float4s
                int r = q >> 5;
                int c4 = q & 31;
                int gm = m0 + r;
                float4 v = make_float4(0.f, 0.f, 0.f, 0.f);
                if (gm < M) v = *reinterpret_cast<const float4*>(A32 + (size_t)gm * CH + c4 * 4);
                __half2 h01 = __float22half2_rn(make_float2(v.x, v.y));
                __half2 h23 = __float22half2_rn(make_float2(v.z, v.w));
                int off = r * ROWB + c4 * 8;
                *reinterpret_cast<uint2*>(smem + AS_T + off) =
                    make_uint2(*reinterpret_cast<uint32_t*>(&h01), *reinterpret_cast<uint32_t*>(&h23));
            }
        } else {
            #pragma unroll
            for (int it = 0; it < 8; it++) {
                int q = tid + it * 256;          // 0..2047 uint4s
                int r = q >> 4;
                int u = q & 15;
                int gm = m0 + r;
                uint4 v = make_uint4(0u, 0u, 0u, 0u);
                if (gm < M) v = *reinterpret_cast<const uint4*>(A16 + (size_t)gm * CH + u * 8);
                *reinterpret_cast<uint4*>(smem + AS_T + r * ROWB + u * 16) = v;
            }
        }
        __syncthreads();

        float acc[2][8][4];
        #pragma unroll
        for (int i = 0; i < 2; i++)
            #pragma unroll
            for (int j = 0; j < 8; j++)
                #pragma unroll
                for (int q = 0; q < 4; q++) acc[i][j][q] = 0.f;

        #pragma unroll
        for (int ks = 0; ks < 8; ks++) {
            const int k0 = ks * 16;
            uint32_t af[2][4];
            ldsm_x4(a_base + k0 * 2,             af[0][0], af[0][1], af[0][2], af[0][3]);
            ldsm_x4(a_base + 16 * ROWB + k0 * 2, af[1][0], af[1][1], af[1][2], af[1][3]);
            uint32_t bf[8][2];
            #pragma unroll
            for (int p = 0; p < 4; p++) {
                uint32_t r0, r1, r2, r3;
                ldsm_x4(b_base + p * 16 * ROWB + k0 * 2, r0, r1, r2, r3);
                bf[2 * p][0] = r0; bf[2 * p][1] = r1;
                bf[2 * p + 1][0] = r2; bf[2 * p + 1][1] = r3;
            }
            #pragma unroll
            for (int i = 0; i < 2; i++)
                #pragma unroll
                for (int j = 0; j < 8; j++)
                    mma_f16(acc[i][j], af[i], bf[j]);
        }

        // epilogue: fp32 (C) and/or fp16 (Ch)
        #pragma unroll
        for (int i = 0; i < 2; i++) {
            #pragma unroll
            for (int half = 0; half < 2; half++) {
                int gm = m0 + mw0 + i * 16 + mq + half * 8;
                if (gm < M) {
                    #pragma unroll
                    for (int j = 0; j < 8; j++) {
                        float2 o = half ? make_float2(acc[i][j][2], acc[i][j][3])
                                        : make_float2(acc[i][j][0], acc[i][j][1]);
                        if (C)
                            *reinterpret_cast<float2*>(C + (size_t)gm * CH + nw0 + j * 8 + nq) = o;
                        if (Ch) {
                            __half2 h = __float22half2_rn(o);
                            *reinterpret_cast<__half2*>(Ch + (size_t)gm * CH + nw0 + j * 8 + nq) = h;
                        }
                    }
                }
            }
        }
        __syncthreads();   // protect A tile before next stage
    }
}

// ---------------- aggr: warp-per-node; aggr_h[n] = t_h[n] - min_nbr t_h[col] ----------------
// Also self-resets g_cur[n] to 0 for the next call (graph-replay safe).
__global__ __launch_bounds__(256) void aggr_kernel(int N) {
    const int gw = (blockIdx.x * blockDim.x + threadIdx.x) >> 5;
    if (gw >= N) return;
    const int n = gw;
    const int lane = threadIdx.x & 31;
    const int rawcnt = g_cur[n];
    const int cnt = min(rawcnt, CAP);
    if (lane == 0) g_cur[n] = 0;    // reset for next call's scatter

    const __half2 hbig = __float2half2_rn(60000.f);
    __half2 a0 = hbig, a1 = hbig;
    __half2 b0 = hbig, b1 = hbig;

    const size_t csr_base = (size_t)n * CAP;

    for (int base = 0; base < cnt; base += 32) {
        int my_col = (base + lane < cnt) ? g_csr[csr_base + base + lane] : 0;
        int lim = min(32, cnt - base);
        int j = 0;
        #pragma unroll 4
        for (; j + 2 <= lim; j += 2) {
            int c0 = __shfl_sync(0xffffffffu, my_col, j);
            int c1 = __shfl_sync(0xffffffffu, my_col, j + 1);
            uint2 v0 = *reinterpret_cast<const uint2*>(g_t_h + (size_t)c0 * CH + lane * 4);
            uint2 v1 = *reinterpret_cast<const uint2*>(g_t_h + (size_t)c1 * CH + lane * 4);
            a0 = __hmin2(a0, *reinterpret_cast<const __half2*>(&v0.x));
            a1 = __hmin2(a1, *reinterpret_cast<const __half2*>(&v0.y));
            b0 = __hmin2(b0, *reinterpret_cast<const __half2*>(&v1.x));
            b1 = __hmin2(b1, *reinterpret_cast<const __half2*>(&v1.y));
        }
        if (j < lim) {
            int c0 = __shfl_sync(0xffffffffu, my_col, j);
            uint2 v0 = *reinterpret_cast<const uint2*>(g_t_h + (size_t)c0 * CH + lane * 4);
            a0 = __hmin2(a0, *reinterpret_cast<const __half2*>(&v0.x));
            a1 = __hmin2(a1, *reinterpret_cast<const __half2*>(&v0.y));
        }
    }

    // overflow spill (empty in practice; correct for any input)
    int novf = g_novf;
    for (int i = 0; i < novf; i++) {
        if (g_ovf_r[i] == n) {
            uint2 v = *reinterpret_cast<const uint2*>(g_t_h + (size_t)g_ovf_c[i] * CH + lane * 4);
            a0 = __hmin2(a0, *reinterpret_cast<const __half2*>(&v.x));
            a1 = __hmin2(a1, *reinterpret_cast<const __half2*>(&v.y));
        }
    }

    a0 = __hmin2(a0, b0);
    a1 = __hmin2(a1, b1);

    uint2 outv;
    if (cnt == 0) {
        __half2 z = __float2half2_rn(0.f);
        outv = make_uint2(*reinterpret_cast<uint32_t*>(&z), *reinterpret_cast<uint32_t*>(&z));
    } else {
        uint2 tv = *reinterpret_cast<const uint2*>(g_t_h + (size_t)n * CH + lane * 4);
        const __half2 t0 = *reinterpret_cast<const __half2*>(&tv.x);
        const __half2 t1 = *reinterpret_cast<const __half2*>(&tv.y);
        float2 d0 = make_float2(__low2float(t0) - __low2float(a0),
                                __high2float(t0) - __high2float(a0));
        float2 d1 = make_float2(__low2float(t1) - __low2float(a1),
                                __high2float(t1) - __high2float(a1));
        __half2 o0 = __float22half2_rn(d0);
        __half2 o1 = __float22half2_rn(d1);
        outv = make_uint2(*reinterpret_cast<uint32_t*>(&o0), *reinterpret_cast<uint32_t*>(&o1));
    }
    *reinterpret_cast<uint2*>(g_aggr_h + (size_t)n * CH + lane * 4) = outv;
}

// ---------------- launch: scatter forks at t=0; init(W) -> gemm1 on stream 0 ----------------
extern "C" void kernel_launch(void* const* d_in, const int* in_sizes, int n_in,
                              void* d_out, int out_size) {
    const float* x  = (const float*)d_in[0];
    const int*   ei = (const int*)d_in[1];
    const float* Wt = (const float*)d_in[2];
    const float* Wp = (const float*)d_in[3];
    float* out = (float*)d_out;

    int N = in_sizes[0] / CH;
    int E = in_sizes[1] / 2;
    const int* row = ei;
    const int* col = ei + E;
    int ngb = (N + 127) / 128;
    int ngrid = ngb < 304 ? ngb : 304;   // persistent: 2 CTAs/SM x 152 SMs

    void *pth = nullptr, *pah = nullptr;
    cudaGetSymbolAddress(&pth, g_t_h);
    cudaGetSymbolAddress(&pah, g_aggr_h);

    cudaFuncSetAttribute(tc_gemm_kernel, cudaFuncAttributeMaxDynamicSharedMemorySize, GSM_TOTAL);

    cudaStream_t s1;
    cudaStreamCreateWithFlags(&s1, cudaStreamNonBlocking);
    cudaEvent_t e_fork, e_join;
    cudaEventCreateWithFlags(&e_fork, cudaEventDisableTiming);
    cudaEventCreateWithFlags(&e_join, cudaEventDisableTiming);

    // fork at t=0: scatter on s1 (g_cur is pre-zeroed by previous call's aggr)
    cudaEventRecord(e_fork, 0);
    cudaStreamWaitEvent(s1, e_fork, 0);
    scatter_kernel<<<((E + 3) / 4 + 255) / 256, 256, 0, s1>>>(row, col, E);

    // stream 0: W convert, then gemm1
    init_kernel<<<(2 * CH * CH + 255) / 256, 256>>>(Wt, Wp);
    tc_gemm_kernel<<<ngrid, 256, GSM_TOTAL>>>(x, nullptr, nullptr, (__half*)pth, N, 0, ngb, 0);

    // join: stream 0 waits for scatter before aggr
    cudaEventRecord(e_join, s1);
    cudaStreamWaitEvent(0, e_join, 0);

    aggr_kernel<<<(N * 32 + 255) / 256, 256>>>(N);
    // gemm2 also resets g_novf for the next call
    tc_gemm_kernel<<<ngrid, 256, GSM_TOTAL>>>(nullptr, (const __half*)pah, out, nullptr, N, 1, ngb, 1);

    cudaEventDestroy(e_fork);
    cudaEventDestroy(e_join);
    cudaStreamDestroy(s1);
}